// round 2
// baseline (speedup 1.0000x reference)
#include <cuda_runtime.h>
#include <cstdint>

#define CDIM 256
#define KCB  8192
#define NTOK 16384
#define TM   16
#define NTHREADS 256
#define OUT_ELEMS (16*256*32*32)

__device__ float g_en[KCB * CDIM];    // normalized codebook [K][C]
__device__ float g_zt[CDIM * NTOK];   // normalized tokens, transposed [C][N]
__device__ int   g_idx[NTOK];

// ---------------- Kernel A: normalize codebook rows ----------------
__global__ void norm_codebook(const float* __restrict__ emb) {
    int row  = blockIdx.x * 8 + (threadIdx.x >> 5);
    int lane = threadIdx.x & 31;
    const float4* w = (const float4*)(emb + (size_t)row * CDIM);
    float4 a = __ldg(w + lane);
    float4 b = __ldg(w + lane + 32);
    float ss = a.x*a.x + a.y*a.y + a.z*a.z + a.w*a.w
             + b.x*b.x + b.y*b.y + b.z*b.z + b.w*b.w;
    #pragma unroll
    for (int s = 16; s; s >>= 1) ss += __shfl_xor_sync(0xffffffffu, ss, s);
    float inv = 1.0f / fmaxf(sqrtf(ss), 1e-12f);
    float4* o = (float4*)(g_en + (size_t)row * CDIM);
    o[lane]      = make_float4(a.x*inv, a.y*inv, a.z*inv, a.w*inv);
    o[lane + 32] = make_float4(b.x*inv, b.y*inv, b.z*inv, b.w*inv);
}

// ---------------- Kernel B: normalize tokens, store transposed ----------------
__global__ void norm_tokens(const float* __restrict__ z) {
    int n  = blockIdx.x * NTHREADS + threadIdx.x;
    int b  = n >> 10;
    int hw = n & 1023;
    const float* zp = z + (size_t)b * CDIM * 1024 + hw;
    float ss = 0.f;
    #pragma unroll 8
    for (int c = 0; c < CDIM; c++) { float v = zp[(size_t)c * 1024]; ss = fmaf(v, v, ss); }
    float inv = 1.0f / fmaxf(sqrtf(ss), 1e-12f);
    #pragma unroll 8
    for (int c = 0; c < CDIM; c++) g_zt[c * NTOK + n] = zp[(size_t)c * 1024] * inv;
}

// ---------------- Kernel M: fused GEMM + argmax ----------------
__global__ void __launch_bounds__(NTHREADS) vq_main() {
    __shared__ float tokS[CDIM][TM];            // 16 KB, [c][t]
    __shared__ unsigned long long red[8][TM];

    int n0 = blockIdx.x * TM;
    for (int i = threadIdx.x; i < CDIM * TM; i += NTHREADS) {
        int c = i >> 4, t = i & (TM - 1);
        tokS[c][t] = g_zt[c * NTOK + n0 + t];
    }
    __syncthreads();

    unsigned long long best[TM];
    #pragma unroll
    for (int t = 0; t < TM; t++) best[t] = 0ull;

    for (int kb = 0; kb < KCB; kb += 2 * NTHREADS) {
        int k0 = kb + threadIdx.x;
        int k1 = k0 + NTHREADS;
        const float4* e0 = (const float4*)(g_en + (size_t)k0 * CDIM);
        const float4* e1 = (const float4*)(g_en + (size_t)k1 * CDIM);
        float acc0[TM], acc1[TM];
        #pragma unroll
        for (int t = 0; t < TM; t++) { acc0[t] = 0.f; acc1[t] = 0.f; }

        #pragma unroll 2
        for (int c4 = 0; c4 < CDIM / 4; c4++) {
            float4 ea = __ldg(e0 + c4);
            float4 eb = __ldg(e1 + c4);
            const float4* ts = (const float4*)(&tokS[c4 * 4][0]);
            #pragma unroll
            for (int j = 0; j < 4; j++) {
                float ev0 = (&ea.x)[j];
                float ev1 = (&eb.x)[j];
                float tv[TM];
                float4 t0 = ts[j*4+0], t1 = ts[j*4+1], t2 = ts[j*4+2], t3 = ts[j*4+3];
                *(float4*)&tv[0]  = t0;
                *(float4*)&tv[4]  = t1;
                *(float4*)&tv[8]  = t2;
                *(float4*)&tv[12] = t3;
                #pragma unroll
                for (int t = 0; t < TM; t++) {
                    acc0[t] = fmaf(ev0, tv[t], acc0[t]);
                    acc1[t] = fmaf(ev1, tv[t], acc1[t]);
                }
            }
        }

        #pragma unroll
        for (int t = 0; t < TM; t++) {
            float v; int ki;
            if (acc0[t] >= acc1[t]) { v = acc0[t]; ki = k0; }   // tie -> smaller k
            else                    { v = acc1[t]; ki = k1; }
            unsigned u = __float_as_uint(v);
            u = (u & 0x80000000u) ? ~u : (u | 0x80000000u);     // order-preserving map
            unsigned long long p = ((unsigned long long)u << 32)
                                 | (unsigned)(KCB - 1 - ki);    // tie -> smaller idx wins max
            if (p > best[t]) best[t] = p;
        }
    }

    int lane = threadIdx.x & 31, warp = threadIdx.x >> 5;
    #pragma unroll
    for (int t = 0; t < TM; t++) {
        unsigned long long p = best[t];
        #pragma unroll
        for (int s = 16; s; s >>= 1) {
            unsigned long long o = __shfl_xor_sync(0xffffffffu, p, s);
            if (o > p) p = o;
        }
        best[t] = p;
    }
    if (lane == 0) {
        #pragma unroll
        for (int t = 0; t < TM; t++) red[warp][t] = best[t];
    }
    __syncthreads();
    if (threadIdx.x < TM) {
        unsigned long long p = red[0][threadIdx.x];
        #pragma unroll
        for (int w = 1; w < 8; w++) if (red[w][threadIdx.x] > p) p = red[w][threadIdx.x];
        g_idx[n0 + threadIdx.x] = (KCB - 1) - (int)(p & 0xFFFFFFFFull);
    }
}

// ---------------- Kernel D: gather codebook rows, transpose to NCHW ----------------
__global__ void gather_out(float* __restrict__ out) {
    __shared__ float s[32][CDIM + 1];
    __shared__ int sidx[32];
    int n0 = blockIdx.x * 32;
    if (threadIdx.x < 32) sidx[threadIdx.x] = g_idx[n0 + threadIdx.x];
    __syncthreads();
    #pragma unroll 4
    for (int i = 0; i < 32; i++) {
        int lin = threadIdx.x + i * NTHREADS;
        int t = lin >> 8, c = lin & 255;
        s[t][c] = g_en[(size_t)sidx[t] * CDIM + c];
    }
    __syncthreads();
    int b   = n0 >> 10;
    int hw0 = n0 & 1023;
    #pragma unroll 4
    for (int i = 0; i < 32; i++) {
        int lin = threadIdx.x + i * NTHREADS;
        int c = lin >> 5, t = lin & 31;
        out[((size_t)b * CDIM + c) * 1024 + hw0 + t] = s[t][c];
    }
}

// ---------------- Kernel E: indices as float ----------------
__global__ void idx_out(float* __restrict__ o) {
    int n = blockIdx.x * NTHREADS + threadIdx.x;
    o[n] = (float)g_idx[n];
}

extern "C" void kernel_launch(void* const* d_in, const int* in_sizes, int n_in,
                              void* d_out, int out_size) {
    const float* z   = (const float*)d_in[0];
    const float* emb = (const float*)d_in[1];
    float* out = (float*)d_out;

    norm_codebook<<<KCB / 8, NTHREADS>>>(emb);
    norm_tokens<<<NTOK / NTHREADS, NTHREADS>>>(z);
    vq_main<<<NTOK / TM, NTHREADS>>>();
    gather_out<<<NTOK / 32, NTHREADS>>>(out);
    if (out_size >= OUT_ELEMS + NTOK)
        idx_out<<<NTOK / NTHREADS, NTHREADS>>>(out + OUT_ELEMS);
}

// round 4
// speedup vs baseline: 2.6021x; 2.6021x over previous
#include <cuda_runtime.h>
#include <cuda_fp16.h>
#include <cstdint>

#define CDIM 256
#define KCB  8192
#define NTOK 16384
#define NTHREADS 256
#define OUT_ELEMS (16*256*32*32)

#define ITERS   64            // codebook tiles of 128 codewords
#define CHUNKS  (ITERS*2)     // k split in halves of 128 channels
#define NSTAGE  3
#define SA_BYTES 65536        // A: 128 tok x 256 ch fp16, rows 512B
#define SB_BYTES 32768        // B chunk: 128 cw x 128 ch fp16, rows 256B
#define SMEM_TOTAL (SA_BYTES + NSTAGE*SB_BYTES)
#define MARGIN 4e-4f

__device__ float  g_en[KCB * CDIM];                    // normalized codebook fp32
__device__ float  g_corr[KCB];                         // 0.5*|e_n|^2
__device__ __align__(16) __half g_e[KCB * CDIM];       // fp16 codebook
__device__ float  g_zf[NTOK * CDIM];                   // normalized tokens fp32
__device__ __align__(16) __half g_z[NTOK * CDIM];      // fp16 tokens
__device__ int    g_idx[NTOK];
__device__ float  g_margin[NTOK];

// ---------------- helpers ----------------
__device__ __forceinline__ uint32_t smem_u32(const void* p) {
    uint32_t a;
    asm("{ .reg .u64 t; cvta.to.shared.u64 t, %1; cvt.u32.u64 %0, t; }" : "=r"(a) : "l"(p));
    return a;
}
#define CP16(dst, src) asm volatile("cp.async.cg.shared.global [%0], [%1], 16;" :: "r"(dst), "l"(src) : "memory")
#define CP_COMMIT()    asm volatile("cp.async.commit_group;" ::: "memory")
#define CP_WAIT1()     asm volatile("cp.async.wait_group 1;" ::: "memory")
#define CP_WAIT0()     asm volatile("cp.async.wait_group 0;" ::: "memory")

__device__ __forceinline__ void ldsm4(uint32_t& r0, uint32_t& r1, uint32_t& r2, uint32_t& r3, uint32_t a) {
    asm volatile("ldmatrix.sync.aligned.m8n8.x4.shared.b16 {%0,%1,%2,%3}, [%4];"
                 : "=r"(r0), "=r"(r1), "=r"(r2), "=r"(r3) : "r"(a));
}
__device__ __forceinline__ void mma16816(float* d, const uint32_t* a, const uint32_t* b) {
    asm volatile("mma.sync.aligned.m16n8k16.row.col.f32.f16.f16.f32 "
                 "{%0,%1,%2,%3}, {%4,%5,%6,%7}, {%8,%9}, {%0,%1,%2,%3};"
                 : "+f"(d[0]), "+f"(d[1]), "+f"(d[2]), "+f"(d[3])
                 : "r"(a[0]), "r"(a[1]), "r"(a[2]), "r"(a[3]), "r"(b[0]), "r"(b[1]));
}
__device__ __forceinline__ unsigned fmap(float v) {
    unsigned u = __float_as_uint(v);
    return (u & 0x80000000u) ? ~u : (u | 0x80000000u);
}
__device__ __forceinline__ float funmap(unsigned u) {
    return __uint_as_float((u & 0x80000000u) ? (u ^ 0x80000000u) : ~u);
}

// ---------------- preprocessing ----------------
__global__ void norm_codebook(const float* __restrict__ emb) {
    int row  = blockIdx.x * 8 + (threadIdx.x >> 5);
    int lane = threadIdx.x & 31;
    const float4* w = (const float4*)(emb + (size_t)row * CDIM);
    float4 a = __ldg(w + lane);
    float4 b = __ldg(w + lane + 32);
    float ss = a.x*a.x + a.y*a.y + a.z*a.z + a.w*a.w
             + b.x*b.x + b.y*b.y + b.z*b.z + b.w*b.w;
    #pragma unroll
    for (int s = 16; s; s >>= 1) ss += __shfl_xor_sync(0xffffffffu, ss, s);
    float inv = 1.0f / fmaxf(sqrtf(ss), 1e-12f);
    float v[8];
    v[0]=a.x*inv; v[1]=a.y*inv; v[2]=a.z*inv; v[3]=a.w*inv;
    v[4]=b.x*inv; v[5]=b.y*inv; v[6]=b.z*inv; v[7]=b.w*inv;
    float4* o = (float4*)(g_en + (size_t)row * CDIM);
    o[lane]      = make_float4(v[0], v[1], v[2], v[3]);
    o[lane + 32] = make_float4(v[4], v[5], v[6], v[7]);
    float ss2 = 0.f;
    #pragma unroll
    for (int j = 0; j < 8; j++) {
        int col = (j < 4) ? (lane*4 + j) : (128 + lane*4 + (j - 4));
        g_e[(size_t)row * CDIM + col] = __float2half_rn(v[j]);
        ss2 = fmaf(v[j], v[j], ss2);
    }
    #pragma unroll
    for (int s = 16; s; s >>= 1) ss2 += __shfl_xor_sync(0xffffffffu, ss2, s);
    if (lane == 0) g_corr[row] = 0.5f * ss2;
}

__global__ void norm_tokens(const float* __restrict__ z) {
    int n  = blockIdx.x * NTHREADS + threadIdx.x;
    int b  = n >> 10;
    int hw = n & 1023;
    const float* zp = z + (size_t)b * CDIM * 1024 + hw;
    float ss = 0.f;
    #pragma unroll 8
    for (int c = 0; c < CDIM; c++) { float v = zp[(size_t)c * 1024]; ss = fmaf(v, v, ss); }
    float inv = 1.0f / fmaxf(sqrtf(ss), 1e-12f);
    #pragma unroll 8
    for (int c = 0; c < CDIM; c++) {
        float v = zp[(size_t)c * 1024] * inv;
        size_t off = (size_t)n * CDIM + c;
        g_zf[off] = v;
        g_z[off]  = __float2half_rn(v);
    }
}

// ---------------- main: HMMA GEMM + fused top-2 ----------------
__global__ void __launch_bounds__(NTHREADS, 1) vq_main() {
    extern __shared__ __align__(128) char smem[];
    const uint32_t sa = smem_u32(smem);
    const int tid = threadIdx.x, lane = tid & 31, wid = tid >> 5;
    const int wm = wid >> 1, wn = wid & 1;
    const int n0 = blockIdx.x * 128;

    // ---- prologue: A tile + first 2 B chunks ----
    {
        #pragma unroll
        for (int j = 0; j < 16; j++) {              // A: 4096 16B units
            int i = tid + j * NTHREADS;
            int r = i >> 5, q = i & 31;
            uint32_t dst = sa + r*512 + ((q*16) ^ ((r & 7) << 4));
            CP16(dst, g_z + (size_t)(n0 + r) * CDIM + q*8);
        }
        #pragma unroll
        for (int j = 0; j < 8; j++) {               // B chunk 0
            int i = tid + j * NTHREADS;
            int r = i >> 4, q = i & 15;
            uint32_t dst = sa + SA_BYTES + r*256 + ((q*16) ^ ((r & 7) << 4));
            CP16(dst, g_e + (size_t)r * CDIM + q*8);
        }
        CP_COMMIT();
        #pragma unroll
        for (int j = 0; j < 8; j++) {               // B chunk 1 (iter0, half1)
            int i = tid + j * NTHREADS;
            int r = i >> 4, q = i & 15;
            uint32_t dst = sa + SA_BYTES + SB_BYTES + r*256 + ((q*16) ^ ((r & 7) << 4));
            CP16(dst, g_e + (size_t)r * CDIM + 128 + q*8);
        }
        CP_COMMIT();
    }

    float acc[2][8][4];
    float v1[4], v2[4];
    int   i1[4];
    #pragma unroll
    for (int rr = 0; rr < 4; rr++) { v1[rr] = -1e30f; v2[rr] = -1e30f; i1[rr] = 0; }

    // lane-derived ldmatrix addressing constants
    const int arow = wm*32 + (lane & 15);                 // + mt*16
    const int akob = (lane >> 4) << 4;                    // bytes
    const int nl   = (lane & 7) | ((lane & 16) >> 1);     // + wn*64 + j*16
    const int bkob = (lane & 8) << 1;                     // bytes
    const int codebase0 = wn*64 + (lane & 3)*2;

    for (int c = 0; c < CHUNKS; c++) {
        int iter = c >> 1, half = c & 1, st = c % 3;
        if (c == CHUNKS - 1) CP_WAIT0(); else CP_WAIT1();
        __syncthreads();

        if (half == 0) {
            #pragma unroll
            for (int mt = 0; mt < 2; mt++)
                #pragma unroll
                for (int f = 0; f < 8; f++)
                    #pragma unroll
                    for (int e = 0; e < 4; e++) acc[mt][f][e] = 0.f;
        }

        const uint32_t sb = sa + SA_BYTES + st * SB_BYTES;
        #pragma unroll
        for (int kk = 0; kk < 8; kk++) {
            uint32_t a[2][4], b[8][2];
            int kAb = (half*128 + kk*16)*2 + akob;        // byte offset in A row
            #pragma unroll
            for (int mt = 0; mt < 2; mt++) {
                int row = arow + mt*16;
                ldsm4(a[mt][0], a[mt][1], a[mt][2], a[mt][3],
                      sa + row*512 + (kAb ^ ((row & 7) << 4)));
            }
            int kBb = kk*32 + bkob;                        // byte offset in B row
            #pragma unroll
            for (int j = 0; j < 4; j++) {
                int n = wn*64 + j*16 + nl;
                ldsm4(b[2*j][0], b[2*j][1], b[2*j+1][0], b[2*j+1][1],
                      sb + n*256 + (kBb ^ ((n & 7) << 4)));
            }
            #pragma unroll
            for (int mt = 0; mt < 2; mt++)
                #pragma unroll
                for (int f = 0; f < 8; f++)
                    mma16816(acc[mt][f], a[mt], b[f]);
        }
        __syncthreads();

        // prefetch chunk c+2
        if (c + 2 < CHUNKS) {
            int ni = (c + 2) >> 1, nh = (c + 2) & 1, ns = (c + 2) % 3;
            uint32_t db = sa + SA_BYTES + ns * SB_BYTES;
            const __half* src0 = g_e + (size_t)ni * 128 * CDIM + nh * 128;
            #pragma unroll
            for (int j = 0; j < 8; j++) {
                int i = tid + j * NTHREADS;
                int r = i >> 4, q = i & 15;
                CP16(db + r*256 + ((q*16) ^ ((r & 7) << 4)),
                     src0 + (size_t)r * CDIM + q*8);
            }
        }
        CP_COMMIT();   // keep group accounting uniform

        if (half == 1) {
            int codebase = iter*128 + codebase0;
            #pragma unroll
            for (int mt = 0; mt < 2; mt++)
                #pragma unroll
                for (int f = 0; f < 8; f++)
                    #pragma unroll
                    for (int e = 0; e < 4; e++) {
                        float s = acc[mt][f][e];
                        int rr = mt*2 + (e >> 1);
                        int code = codebase + f*8 + (e & 1);
                        if (s > v1[rr]) { v2[rr] = v1[rr]; v1[rr] = s; i1[rr] = code; }
                        else if (s > v2[rr]) v2[rr] = s;
                    }
        }
    }

    // ---- reduction ----
    __syncthreads();
    unsigned long long* SK = (unsigned long long*)smem;          // [2][128]
    float* SV2 = (float*)(smem + 2*128*8);                       // [2][128]

    #pragma unroll
    for (int rr = 0; rr < 4; rr++) {
        unsigned long long k = ((unsigned long long)fmap(v1[rr]) << 32)
                             | (unsigned)(KCB - 1 - i1[rr]);
        float a1 = v1[rr], a2 = v2[rr];
        #pragma unroll
        for (int x = 1; x <= 2; x <<= 1) {
            unsigned long long ok = __shfl_xor_sync(0xffffffffu, k, x);
            float b1 = __shfl_xor_sync(0xffffffffu, a1, x);
            float b2 = __shfl_xor_sync(0xffffffffu, a2, x);
            a2 = fmaxf(fmaxf(a2, b2), fminf(a1, b1));
            if (ok > k) { k = ok; a1 = b1; }
        }
        if ((lane & 3) == 0) {
            int m = wm*32 + (rr >> 1)*16 + (rr & 1)*8 + (lane >> 2);
            SK[wn*128 + m] = k;
            SV2[wn*128 + m] = a2;
        }
    }
    __syncthreads();
    if (tid < 128) {
        unsigned long long k0 = SK[tid], k1 = SK[128 + tid];
        float s20 = SV2[tid], s21 = SV2[128 + tid];
        float v10 = funmap((unsigned)(k0 >> 32));
        float v11 = funmap((unsigned)(k1 >> 32));
        float v2f = fmaxf(fmaxf(s20, s21), fminf(v10, v11));
        unsigned long long kw = (k1 > k0) ? k1 : k0;
        float v1f = (k1 > k0) ? v11 : v10;
        int idx = (KCB - 1) - (int)(kw & 0xFFFF);
        g_idx[n0 + tid] = idx;
        g_margin[n0 + tid] = v1f - v2f;
    }
}

// ---------------- exact fp32 re-rank for small-margin tokens ----------------
__global__ void __launch_bounds__(128) rerank() {
    int n = blockIdx.x;
    if (g_margin[n] >= MARGIN) return;
    __shared__ float tz[CDIM];
    __shared__ unsigned long long red[4];
    for (int c = threadIdx.x; c < CDIM; c += 128) tz[c] = g_zf[(size_t)n * CDIM + c];
    __syncthreads();
    unsigned long long best = 0ull;
    for (int k = threadIdx.x; k < KCB; k += 128) {
        const float4* e = (const float4*)(g_en + (size_t)k * CDIM);
        float s = 0.f;
        #pragma unroll 8
        for (int c4 = 0; c4 < CDIM/4; c4++) {
            float4 ev = __ldg(e + c4);
            s = fmaf(ev.x, tz[c4*4+0], s);
            s = fmaf(ev.y, tz[c4*4+1], s);
            s = fmaf(ev.z, tz[c4*4+2], s);
            s = fmaf(ev.w, tz[c4*4+3], s);
        }
        s -= g_corr[k];
        unsigned long long p = ((unsigned long long)fmap(s) << 32)
                             | (unsigned)(KCB - 1 - k);
        if (p > best) best = p;
    }
    #pragma unroll
    for (int sft = 16; sft; sft >>= 1) {
        unsigned long long o = __shfl_xor_sync(0xffffffffu, best, sft);
        if (o > best) best = o;
    }
    int lane = threadIdx.x & 31, warp = threadIdx.x >> 5;
    if (lane == 0) red[warp] = best;
    __syncthreads();
    if (threadIdx.x == 0) {
        unsigned long long p = red[0];
        #pragma unroll
        for (int w = 1; w < 4; w++) if (red[w] > p) p = red[w];
        g_idx[n] = (KCB - 1) - (int)(p & 0xFFFFFFFFull);
    }
}

// ---------------- output ----------------
__global__ void gather_out(float* __restrict__ out) {
    __shared__ float s[32][CDIM + 1];
    __shared__ int sidx[32];
    int n0 = blockIdx.x * 32;
    if (threadIdx.x < 32) sidx[threadIdx.x] = g_idx[n0 + threadIdx.x];
    __syncthreads();
    #pragma unroll 4
    for (int i = 0; i < 32; i++) {
        int lin = threadIdx.x + i * NTHREADS;
        int t = lin >> 8, c = lin & 255;
        s[t][c] = g_en[(size_t)sidx[t] * CDIM + c];
    }
    __syncthreads();
    int b   = n0 >> 10;
    int hw0 = n0 & 1023;
    #pragma unroll 4
    for (int i = 0; i < 32; i++) {
        int lin = threadIdx.x + i * NTHREADS;
        int c = lin >> 5, t = lin & 31;
        out[((size_t)b * CDIM + c) * 1024 + hw0 + t] = s[t][c];
    }
}

__global__ void idx_out(float* __restrict__ o) {
    int n = blockIdx.x * NTHREADS + threadIdx.x;
    o[n] = (float)g_idx[n];
}

extern "C" void kernel_launch(void* const* d_in, const int* in_sizes, int n_in,
                              void* d_out, int out_size) {
    const float* z   = (const float*)d_in[0];
    const float* emb = (const float*)d_in[1];
    float* out = (float*)d_out;

    static int configured = 0;
    if (!configured) {
        cudaFuncSetAttribute(vq_main, cudaFuncAttributeMaxDynamicSharedMemorySize, SMEM_TOTAL);
        configured = 1;
    }

    norm_codebook<<<KCB / 8, NTHREADS>>>(emb);
    norm_tokens<<<NTOK / NTHREADS, NTHREADS>>>(z);
    vq_main<<<NTOK / 128, NTHREADS, SMEM_TOTAL>>>();
    rerank<<<NTOK, 128>>>();
    gather_out<<<NTOK / 32, NTHREADS>>>(out);
    if (out_size >= OUT_ELEMS + NTOK)
        idx_out<<<NTOK / NTHREADS, NTHREADS>>>(out + OUT_ELEMS);
}